// round 14
// baseline (speedup 1.0000x reference)
#include <cuda_runtime.h>
#include <cuda_fp16.h>
#include <stdint.h>

#define FDIM   1024
#define BATCH  256
#define NCLS   1000
#define CPAD   1024
#define KROW   65536
#define CB     16          // class blocks of 64
#define FS     8           // f slices of 128
#define FPC    128
#define THREADS 512
#define TSTRIDE 65         // pair-tile row stride in words
#define FTILE  (64 * TSTRIDE)          // words per f-tile (4160)
#define EPOCH_F 4
#define NEPOCH (FPC / EPOCH_F)         // 32

// smem word layout: tiles [EPOCH_F][FTILE] | staging [EPOCH_F][4096] | metaring [2][1024] uint2
#define TL_WO  0
#define ST_WO  (EPOCH_F * FTILE)                 // 16640
#define MR_WO  (ST_WO + EPOCH_F * 4096)          // 33024
#define SMEM_BYTES ((MR_WO + 2 * 1024 * 2) * 4)  // 148480

// ---------------- static device scratch ----------------
__device__ uint2 g_meta[FDIM * BATCH];                   // [f][b]: {t*260, half2(1-l0, l0)}
__device__ float g_part[(size_t)FS * BATCH * CPAD];      // [fs][b][c]
__device__ float g_rspart[FS * CPAD];                    // [fs][c]

__device__ __forceinline__ uint32_t smem_u32(const void* p) {
    uint32_t a;
    asm("{ .reg .u64 t; cvta.to.shared.u64 t, %1; cvt.u32.u64 %0, t; }" : "=r"(a) : "l"(p));
    return a;
}
__device__ __forceinline__ void cpa16(uint32_t dst, const void* src) {
    asm volatile("cp.async.cg.shared.global [%0], [%1], 16;"
                 :: "r"(dst), "l"((uint64_t)__cvta_generic_to_global(src)) : "memory");
}

// ---------------- Kernel 1: precomputed meta (transposed store) ----------------
__global__ void __launch_bounds__(1024) embed_k(const float* __restrict__ x,
                                                const float* __restrict__ mn,
                                                const float* __restrict__ mx) {
    __shared__ uint2 sm[32][33];
    const int tx = threadIdx.x & 31;
    const int ty = threadIdx.x >> 5;
    const int f0 = blockIdx.x * 32;
    const int b0 = blockIdx.y * 32;

    const float mnv = mn[0], mxv = mx[0];
    const float s = (x[(size_t)(b0 + ty) * FDIM + f0 + tx] - mnv) / (mxv - mnv) * 63.0f;

    uint2 m;
    if (s >= 0.0f && s <= 63.0f) {
        int t = (int)s;
        if (t > 62) t = 62;
        const float l0 = s - (float)t;                    // weight of vertex t+1
        const __half2 lam2 = __floats2half2_rn(1.0f - l0, l0);
        m.x = (uint32_t)t * (TSTRIDE * 4);
        m.y = *(const uint32_t*)&lam2;
    } else {
        m.x = 63u * (TSTRIDE * 4);                        // zero row sink
        m.y = 0u;                                         // zero lambda
    }
    sm[ty][tx] = m;
    __syncthreads();
    g_meta[(size_t)(f0 + ty) * BATCH + b0 + tx] = sm[tx][ty];
}

// ---------------- Kernel 2: f16-pair gather, cp.async staged W ----------------
// CTA: 64 classes (cb) x 128 f (fs) x 256 b. tile[f4][t][c] = half2(W[c][t], W[c][t+1]).
// Gather: warp w (0..15) -> b in [16w,16w+16); lane -> classes {lane, lane+32}.
__global__ void __launch_bounds__(THREADS, 1) gather_k(const float* __restrict__ W) {
    extern __shared__ uint32_t smw[];
    uint32_t* tiles    = smw + TL_WO;
    float*    staging  = (float*)(smw + ST_WO);
    uint2*    metaring = (uint2*)(smw + MR_WO);
    const uint32_t smbase = smem_u32(smw);

    const int tid  = threadIdx.x;
    const int lane = tid & 31;
    const int w    = tid >> 5;       // 0..15
    const int ly   = lane >> 4;
    const int g    = lane & 15;
    const int cb   = blockIdx.x;     // 0..15
    const int fs   = blockIdx.y;     // 0..7
    const int fbase = fs * FPC;

    // conversion role: pass p (0..1) -> class row p*32 + w*2 + ly, cols 4g..4g+3
    int rl[2];
    #pragma unroll
    for (int p = 0; p < 2; p++) rl[p] = p * 32 + w * 2 + ly;

    // cp.async role: f-in-epoch cf = tid>>7; class (tid&127)>>1; half tid&1 (32 floats/thread)
    const int cf = tid >> 7;
    const int cc = (tid & 127) >> 1;
    const int ch = tid & 1;
    int crow = cb * 64 + cc; if (crow > NCLS - 1) crow = NCLS - 1;
    const float* csrc = W + (size_t)crow * KROW + (size_t)fbase * 64 + cf * 64 + ch * 32;
    const uint32_t cdst = smbase + (uint32_t)(ST_WO + cf * 4096 + cc * 64 + ch * 32) * 4u;
    // meta cp.async: f-in-epoch mfi = tid>>7, 2 consecutive b entries
    const uint2* msrc = g_meta + (size_t)(fbase + cf) * BATCH + (tid & 127) * 2;
    const uint32_t mdst0 = smbase + (uint32_t)MR_WO * 4u + (uint32_t)(cf * 256 + (tid & 127) * 2) * 8u;

    uint32_t acch[2][16];
    float    accf[2][16];
    #pragma unroll
    for (int k = 0; k < 2; k++)
        #pragma unroll
        for (int j = 0; j < 16; j++) { acch[k][j] = 0u; accf[k][j] = 0.f; }
    float rs[2] = {0.f, 0.f};

    auto issue = [&](int e) {
        const float* s = csrc + (size_t)e * 256;          // 4 f * 64 cols per epoch
        #pragma unroll
        for (int k = 0; k < 8; k++) cpa16(cdst + (uint32_t)k * 16u, s + k * 4);
        cpa16(mdst0 + (uint32_t)(e & 1) * 8192u, msrc + (size_t)e * 1024);
        asm volatile("cp.async.commit_group;" ::: "memory");
    };

    issue(0);

    for (int e = 0; e < NEPOCH; e++) {
        const int mslot = e & 1;

        asm volatile("cp.async.wait_group 0;" ::: "memory");
        __syncthreads();                                  // staging + meta visible to all

        // ---- convert staging -> pair tiles + rowsum ----
        #pragma unroll
        for (int f4 = 0; f4 < EPOCH_F; f4++) {
            const float* st = staging + f4 * 4096;
            uint32_t* tb = tiles + f4 * FTILE;
            #pragma unroll
            for (int p = 0; p < 2; p++) {
                const float4 v = *(const float4*)(st + rl[p] * 64 + 4 * g);
                const float nx = __shfl_down_sync(0xffffffffu, v.x, 1);
                rs[p] += (v.x + v.y) + (v.z + v.w);
                uint32_t pr[4]; __half2 h;
                h = __floats2half2_rn(v.x, v.y);  pr[0] = *(uint32_t*)&h;
                h = __floats2half2_rn(v.y, v.z);  pr[1] = *(uint32_t*)&h;
                h = __floats2half2_rn(v.z, v.w);  pr[2] = *(uint32_t*)&h;
                h = __floats2half2_rn(v.w, nx);   pr[3] = *(uint32_t*)&h;
                if (g == 15) pr[3] = 0u;          // t=63 row: zero sink
                #pragma unroll
                for (int i = 0; i < 4; i++)
                    tb[(4 * g + i) * TSTRIDE + rl[p]] = pr[i];
            }
        }
        __syncthreads();                                  // all staging reads done; tiles visible

        if (e + 1 < NEPOCH) issue(e + 1);                 // overwrite staging; lands during gather

        // ---- gather 4 f's: per b: 2 conflict-free LDS.32 + 2 HFMA2 ----
        #pragma unroll
        for (int f4 = 0; f4 < EPOCH_F; f4++) {
            const char* tb = (const char*)(tiles + f4 * FTILE);
            const uint4* mb = (const uint4*)(metaring + mslot * 1024 + f4 * 256 + w * 16);
            #pragma unroll
            for (int q = 0; q < 8; q++) {
                const uint4 mq = mb[q];
                {
                    const int j = 2 * q;
                    const uint32_t* pb = (const uint32_t*)(tb + mq.x) + lane;
                    const uint32_t p0 = pb[0];
                    const uint32_t p1 = pb[32];
                    const __half2 l2 = *(const __half2*)&mq.y;
                    __half2 a0 = *(__half2*)&acch[0][j];
                    __half2 a1 = *(__half2*)&acch[1][j];
                    a0 = __hfma2(l2, *(const __half2*)&p0, a0);
                    a1 = __hfma2(l2, *(const __half2*)&p1, a1);
                    acch[0][j] = *(uint32_t*)&a0;
                    acch[1][j] = *(uint32_t*)&a1;
                }
                {
                    const int j = 2 * q + 1;
                    const uint32_t* pb = (const uint32_t*)(tb + mq.z) + lane;
                    const uint32_t p0 = pb[0];
                    const uint32_t p1 = pb[32];
                    const __half2 l2 = *(const __half2*)&mq.w;
                    __half2 a0 = *(__half2*)&acch[0][j];
                    __half2 a1 = *(__half2*)&acch[1][j];
                    a0 = __hfma2(l2, *(const __half2*)&p0, a0);
                    a1 = __hfma2(l2, *(const __half2*)&p1, a1);
                    acch[0][j] = *(uint32_t*)&a0;
                    acch[1][j] = *(uint32_t*)&a1;
                }
            }
        }

        // ---- drain f16 accumulators to fp32 every 4 epochs (16 f) ----
        if ((e & 3) == 3) {
            #pragma unroll
            for (int k = 0; k < 2; k++)
                #pragma unroll
                for (int j = 0; j < 16; j++) {
                    const float2 f2v = __half22float2(*(const __half2*)&acch[k][j]);
                    accf[k][j] += f2v.x + f2v.y;
                    acch[k][j] = 0u;
                }
        }
    }

    // ---- rowsum: reduce over the 16 column groups ----
    #pragma unroll
    for (int p = 0; p < 2; p++) {
        float r = rs[p];
        r += __shfl_xor_sync(0xffffffffu, r, 1);
        r += __shfl_xor_sync(0xffffffffu, r, 2);
        r += __shfl_xor_sync(0xffffffffu, r, 4);
        r += __shfl_xor_sync(0xffffffffu, r, 8);
        if (g == 0)
            g_rspart[fs * CPAD + cb * 64 + rl[p]] = r;
    }

    // ---- store partials (coalesced 128B per half) ----
    #pragma unroll
    for (int j = 0; j < 16; j++) {
        float* pp = g_part + ((size_t)fs * BATCH + w * 16 + j) * CPAD + cb * 64;
        pp[lane]      = accf[0][j];
        pp[lane + 32] = accf[1][j];
    }
}

// ---------------- Kernel 3: reduce partials + rowsum term ----------------
__global__ void __launch_bounds__(256) epi_k(const float* __restrict__ mn,
                                             const float* __restrict__ mx,
                                             float* __restrict__ out) {
    const int b = blockIdx.x;
    const float mnv = mn[0], mxv = mx[0];
    const float sc = mxv - mnv;
    for (int c = threadIdx.x; c < NCLS; c += 256) {
        float s = 0.f, rsum = 0.f;
        #pragma unroll
        for (int fsl = 0; fsl < FS; fsl++) {
            s    += g_part[((size_t)fsl * BATCH + b) * CPAD + c];
            rsum += g_rspart[fsl * CPAD + c];
        }
        out[(size_t)b * NCLS + c] = sc * s + mnv * rsum;
    }
}

// ---------------- launch ----------------
extern "C" void kernel_launch(void* const* d_in, const int* in_sizes, int n_in,
                              void* d_out, int out_size) {
    const float* x  = (const float*)d_in[0];
    const float* mn = (const float*)d_in[1];
    const float* mx = (const float*)d_in[2];
    const float* W  = (const float*)d_in[3];
    float* out = (float*)d_out;

    embed_k<<<dim3(32, 8), 1024>>>(x, mn, mx);

    cudaFuncSetAttribute(gather_k, cudaFuncAttributeMaxDynamicSharedMemorySize, SMEM_BYTES);
    gather_k<<<dim3(CB, FS), THREADS, SMEM_BYTES>>>(W);

    epi_k<<<BATCH, 256>>>(mn, mx, out);
}

// round 15
// speedup vs baseline: 1.4136x; 1.4136x over previous
#include <cuda_runtime.h>
#include <cuda_fp16.h>
#include <stdint.h>

#define FDIM   1024
#define BATCH  256
#define NCLS   1000
#define CPAD   1024
#define KROW   65536
#define CB     16          // class blocks of 64
#define FS     8           // f slices of 128
#define FPC    128
#define THREADS 512
#define TSTRIDE 66         // pair-tile row stride in words (even: STS.64-aligned)
#define FTILE  (64 * TSTRIDE)          // words per f-tile (4224)
#define EPOCH_F 4
#define NEPOCH (FPC / EPOCH_F)         // 32

// dynamic smem layout (words): tiles [2][EPOCH_F][FTILE], then meta [2][EPOCH_F*256] uint2
#define TILE_WORDS (2 * EPOCH_F * FTILE)
#define META_OFF_W TILE_WORDS
#define SMEM_BYTES (TILE_WORDS * 4 + 2 * EPOCH_F * 256 * 8)   // 151552

// ---------------- static device scratch ----------------
__device__ uint2 g_meta[FDIM * BATCH];                   // [f][b]: {t*264, half2(1-l0, l0)}
__device__ float g_part[(size_t)FS * BATCH * CPAD];      // [fs][b][c]
__device__ float g_rspart[FS * CPAD];                    // [fs][c]

// ---------------- Kernel 1: precomputed meta (transposed store) ----------------
__global__ void __launch_bounds__(1024) embed_k(const float* __restrict__ x,
                                                const float* __restrict__ mn,
                                                const float* __restrict__ mx) {
    __shared__ uint2 sm[32][33];
    const int tx = threadIdx.x & 31;
    const int ty = threadIdx.x >> 5;
    const int f0 = blockIdx.x * 32;
    const int b0 = blockIdx.y * 32;

    const float mnv = mn[0], mxv = mx[0];
    const float s = (x[(size_t)(b0 + ty) * FDIM + f0 + tx] - mnv) / (mxv - mnv) * 63.0f;

    uint2 m;
    if (s >= 0.0f && s <= 63.0f) {
        int t = (int)s;
        if (t > 62) t = 62;
        const float l0 = s - (float)t;                    // weight of vertex t+1
        const __half2 lam2 = __floats2half2_rn(1.0f - l0, l0);
        m.x = (uint32_t)t * (TSTRIDE * 4);
        m.y = *(const uint32_t*)&lam2;
    } else {
        m.x = 63u * (TSTRIDE * 4);                        // zero row sink
        m.y = 0u;                                         // zero lambda
    }
    sm[ty][tx] = m;
    __syncthreads();
    g_meta[(size_t)(f0 + ty) * BATCH + b0 + tx] = sm[tx][ty];
}

// ---------------- Kernel 2: f16-pair gather, 4-f epochs, STS.64 fill ----------------
// CTA: 64 classes (cb) x 128 f (fs) x 256 b. tile[f4][t][c] = half2(W[c][t], W[c][t+1]).
// Fill: thread (w,ly,g) owns class pair {2pr, 2pr+1}, pr = w*2+ly, col-group g.
// Gather: warp w (0..15) -> b in [16w,16w+16); lane -> classes {lane, lane+32}.
__global__ void __launch_bounds__(THREADS, 1) gather_k(const float* __restrict__ W) {
    extern __shared__ uint32_t smw[];
    uint32_t* tiles = smw;
    uint2*    meta  = (uint2*)(smw + META_OFF_W);

    const int tid  = threadIdx.x;
    const int lane = tid & 31;
    const int w    = tid >> 5;       // 0..15
    const int ly   = lane >> 4;
    const int g    = lane & 15;
    const int cb   = blockIdx.x;     // 0..15
    const int fs   = blockIdx.y;     // 0..7
    const int fbase = fs * FPC;

    // fill: class pair {2pr, 2pr+1}, cols 4g..4g+3 (two coalesced float4 rows)
    const int pr = w * 2 + ly;       // 0..31
    const float* wp[2];
    #pragma unroll
    for (int p = 0; p < 2; p++) {
        int row = cb * 64 + 2 * pr + p;
        if (row > NCLS - 1) row = NCLS - 1;
        wp[p] = W + (size_t)row * KROW + (size_t)fbase * 64 + g * 4;
    }
    const uint2* mp0 = g_meta + (size_t)(fbase + (tid >> 8)) * BATCH + (tid & 255);
    const uint2* mp1 = mp0 + 2 * BATCH;

    uint32_t acch[2][16];
    float    accf[2][16];
    #pragma unroll
    for (int k = 0; k < 2; k++)
        #pragma unroll
        for (int j = 0; j < 16; j++) { acch[k][j] = 0u; accf[k][j] = 0.f; }
    float rs[2] = {0.f, 0.f};

    // prologue prefetch: epoch 0 (f = 0..3)
    float4 wv[2][EPOCH_F];
    #pragma unroll
    for (int p = 0; p < 2; p++)
        #pragma unroll
        for (int f4 = 0; f4 < EPOCH_F; f4++)
            wv[p][f4] = *(const float4*)(wp[p] + f4 * 64);
    uint2 mr0 = mp0[0], mr1 = mp1[0];

    for (int e = 0; e < NEPOCH; e++) {
        const int buf = e & 1;
        uint32_t* tbase = tiles + buf * (EPOCH_F * FTILE);

        // ---- fill pair sub-tiles + rowsum: 4 STS.64 per f (both classes per store) ----
        #pragma unroll
        for (int f4 = 0; f4 < EPOCH_F; f4++) {
            uint32_t* tb = tbase + f4 * FTILE;
            const float4 v0 = wv[0][f4];
            const float4 v1 = wv[1][f4];
            const float nx0 = __shfl_down_sync(0xffffffffu, v0.x, 1);
            const float nx1 = __shfl_down_sync(0xffffffffu, v1.x, 1);
            rs[0] += (v0.x + v0.y) + (v0.z + v0.w);
            rs[1] += (v1.x + v1.y) + (v1.z + v1.w);
            uint32_t pa[4], pb2[4]; __half2 h;
            h = __floats2half2_rn(v0.x, v0.y);  pa[0] = *(uint32_t*)&h;
            h = __floats2half2_rn(v0.y, v0.z);  pa[1] = *(uint32_t*)&h;
            h = __floats2half2_rn(v0.z, v0.w);  pa[2] = *(uint32_t*)&h;
            h = __floats2half2_rn(v0.w, nx0);   pa[3] = *(uint32_t*)&h;
            h = __floats2half2_rn(v1.x, v1.y);  pb2[0] = *(uint32_t*)&h;
            h = __floats2half2_rn(v1.y, v1.z);  pb2[1] = *(uint32_t*)&h;
            h = __floats2half2_rn(v1.z, v1.w);  pb2[2] = *(uint32_t*)&h;
            h = __floats2half2_rn(v1.w, nx1);   pb2[3] = *(uint32_t*)&h;
            if (g == 15) { pa[3] = 0u; pb2[3] = 0u; }     // t=63 row: zero sink
            #pragma unroll
            for (int i = 0; i < 4; i++) {
                uint2* d = (uint2*)(tb + (4 * g + i) * TSTRIDE + 2 * pr);
                *d = make_uint2(pa[i], pb2[i]);           // STS.64: classes 2pr, 2pr+1
            }
        }
        meta[buf * (EPOCH_F * 256) + tid]       = mr0;
        meta[buf * (EPOCH_F * 256) + tid + 512] = mr1;

        __syncthreads();

        // ---- refill registers for epoch e+1 ----
        if (e + 1 < NEPOCH) {
            const size_t off = (size_t)(EPOCH_F * (e + 1)) * 64;
            #pragma unroll
            for (int p = 0; p < 2; p++)
                #pragma unroll
                for (int f4 = 0; f4 < EPOCH_F; f4++)
                    wv[p][f4] = *(const float4*)(wp[p] + off + f4 * 64);
            mr0 = mp0[(size_t)(EPOCH_F * (e + 1)) * BATCH];
            mr1 = mp1[(size_t)(EPOCH_F * (e + 1)) * BATCH];
        }

        // ---- gather 4 f's: per b: 2 conflict-free LDS.32 + 2 HFMA2 ----
        #pragma unroll
        for (int f4 = 0; f4 < EPOCH_F; f4++) {
            const char* tb = (const char*)(tbase + f4 * FTILE);
            const uint4* mb = (const uint4*)(meta + buf * (EPOCH_F * 256) + f4 * 256 + w * 16);
            #pragma unroll
            for (int q = 0; q < 8; q++) {
                const uint4 mq = mb[q];
                {
                    const int j = 2 * q;
                    const uint32_t* pb = (const uint32_t*)(tb + mq.x) + lane;
                    const uint32_t p0 = pb[0];
                    const uint32_t p1 = pb[32];
                    const __half2 l2 = *(const __half2*)&mq.y;
                    __half2 a0 = *(__half2*)&acch[0][j];
                    __half2 a1 = *(__half2*)&acch[1][j];
                    a0 = __hfma2(l2, *(const __half2*)&p0, a0);
                    a1 = __hfma2(l2, *(const __half2*)&p1, a1);
                    acch[0][j] = *(uint32_t*)&a0;
                    acch[1][j] = *(uint32_t*)&a1;
                }
                {
                    const int j = 2 * q + 1;
                    const uint32_t* pb = (const uint32_t*)(tb + mq.z) + lane;
                    const uint32_t p0 = pb[0];
                    const uint32_t p1 = pb[32];
                    const __half2 l2 = *(const __half2*)&mq.w;
                    __half2 a0 = *(__half2*)&acch[0][j];
                    __half2 a1 = *(__half2*)&acch[1][j];
                    a0 = __hfma2(l2, *(const __half2*)&p0, a0);
                    a1 = __hfma2(l2, *(const __half2*)&p1, a1);
                    acch[0][j] = *(uint32_t*)&a0;
                    acch[1][j] = *(uint32_t*)&a1;
                }
            }
        }

        // ---- drain f16 accumulators to fp32 every 4 epochs (16 f) ----
        if ((e & 3) == 3) {
            #pragma unroll
            for (int k = 0; k < 2; k++)
                #pragma unroll
                for (int j = 0; j < 16; j++) {
                    const float2 f2v = __half22float2(*(const __half2*)&acch[k][j]);
                    accf[k][j] += f2v.x + f2v.y;
                    acch[k][j] = 0u;
                }
        }
    }

    // ---- rowsum: reduce over the 16 column groups ----
    #pragma unroll
    for (int p = 0; p < 2; p++) {
        float r = rs[p];
        r += __shfl_xor_sync(0xffffffffu, r, 1);
        r += __shfl_xor_sync(0xffffffffu, r, 2);
        r += __shfl_xor_sync(0xffffffffu, r, 4);
        r += __shfl_xor_sync(0xffffffffu, r, 8);
        if (g == 0)
            g_rspart[fs * CPAD + cb * 64 + 2 * pr + p] = r;
    }

    // ---- store partials (coalesced 128B per half) ----
    #pragma unroll
    for (int j = 0; j < 16; j++) {
        float* pp = g_part + ((size_t)fs * BATCH + w * 16 + j) * CPAD + cb * 64;
        pp[lane]      = accf[0][j];
        pp[lane + 32] = accf[1][j];
    }
}

// ---------------- Kernel 3: reduce partials + rowsum term ----------------
__global__ void __launch_bounds__(256) epi_k(const float* __restrict__ mn,
                                             const float* __restrict__ mx,
                                             float* __restrict__ out) {
    const int b = blockIdx.x;
    const float mnv = mn[0], mxv = mx[0];
    const float sc = mxv - mnv;
    for (int c = threadIdx.x; c < NCLS; c += 256) {
        float s = 0.f, rsum = 0.f;
        #pragma unroll
        for (int fsl = 0; fsl < FS; fsl++) {
            s    += g_part[((size_t)fsl * BATCH + b) * CPAD + c];
            rsum += g_rspart[fsl * CPAD + c];
        }
        out[(size_t)b * NCLS + c] = sc * s + mnv * rsum;
    }
}

// ---------------- launch ----------------
extern "C" void kernel_launch(void* const* d_in, const int* in_sizes, int n_in,
                              void* d_out, int out_size) {
    const float* x  = (const float*)d_in[0];
    const float* mn = (const float*)d_in[1];
    const float* mx = (const float*)d_in[2];
    const float* W  = (const float*)d_in[3];
    float* out = (float*)d_out;

    embed_k<<<dim3(32, 8), 1024>>>(x, mn, mx);

    cudaFuncSetAttribute(gather_k, cudaFuncAttributeMaxDynamicSharedMemorySize, SMEM_BYTES);
    gather_k<<<dim3(CB, FS), THREADS, SMEM_BYTES>>>(W);

    epi_k<<<BATCH, 256>>>(mn, mx, out);
}

// round 16
// speedup vs baseline: 1.7037x; 1.2053x over previous
#include <cuda_runtime.h>
#include <cuda_fp16.h>
#include <stdint.h>

#define FDIM   1024
#define BATCH  256
#define NCLS   1000
#define CPAD   1024
#define KROW   65536
#define CB     16          // class blocks of 64
#define FS     9           // f slices (uneven epochs: 4x29 + 5x28)
#define THREADS 512
#define TSTRIDE 65         // pair-tile row stride in words
#define FTILE  (64 * TSTRIDE)          // words per f-tile (4160)
#define EPOCH_F 4

// dynamic smem layout (words): tiles [2][EPOCH_F][FTILE], then meta [2][EPOCH_F*256] uint2
#define TILE_WORDS (2 * EPOCH_F * FTILE)
#define META_OFF_W TILE_WORDS
#define SMEM_BYTES (TILE_WORDS * 4 + 2 * EPOCH_F * 256 * 8)   // 149504

// ---------------- static device scratch ----------------
__device__ uint2 g_meta[FDIM * BATCH];                   // [f][b]: {t*260, half2(1-l0, l0)}
__device__ float g_part[(size_t)FS * BATCH * CPAD];      // [fs][b][c]
__device__ float g_rspart[FS * CPAD];                    // [fs][c]

// ---------------- Kernel 1: precomputed meta (transposed store) ----------------
__global__ void __launch_bounds__(1024) embed_k(const float* __restrict__ x,
                                                const float* __restrict__ mn,
                                                const float* __restrict__ mx) {
    __shared__ uint2 sm[32][33];
    const int tx = threadIdx.x & 31;
    const int ty = threadIdx.x >> 5;
    const int f0 = blockIdx.x * 32;
    const int b0 = blockIdx.y * 32;

    const float mnv = mn[0], mxv = mx[0];
    const float s = (x[(size_t)(b0 + ty) * FDIM + f0 + tx] - mnv) / (mxv - mnv) * 63.0f;

    uint2 m;
    if (s >= 0.0f && s <= 63.0f) {
        int t = (int)s;
        if (t > 62) t = 62;
        const float l0 = s - (float)t;                    // weight of vertex t+1
        const __half2 lam2 = __floats2half2_rn(1.0f - l0, l0);
        m.x = (uint32_t)t * (TSTRIDE * 4);
        m.y = *(const uint32_t*)&lam2;
    } else {
        m.x = 63u * (TSTRIDE * 4);                        // zero row sink
        m.y = 0u;                                         // zero lambda
    }
    sm[ty][tx] = m;
    __syncthreads();
    g_meta[(size_t)(f0 + ty) * BATCH + b0 + tx] = sm[tx][ty];
}

// ---------------- Kernel 2: f16-pair gather, 4-f epochs, 9 uneven f-slices ----------------
// CTA: 64 classes (cb) x slice f-range x 256 b. tile[f4][t][c] = half2(W[c][t], W[c][t+1]).
// Gather: warp w (0..15) -> b in [16w,16w+16); lane -> classes {lane, lane+32}.
__global__ void __launch_bounds__(THREADS, 1) gather_k(const float* __restrict__ W) {
    extern __shared__ uint32_t smw[];
    uint32_t* tiles = smw;
    uint2*    meta  = (uint2*)(smw + META_OFF_W);

    const int tid  = threadIdx.x;
    const int lane = tid & 31;
    const int w    = tid >> 5;       // 0..15
    const int ly   = lane >> 4;
    const int g    = lane & 15;
    const int cb   = blockIdx.x;     // 0..15
    const int fs   = blockIdx.y;     // 0..8
    // uneven epoch partition: slices 0..3 get 29 epochs, 4..8 get 28 (total 256)
    const int ebase = (fs < 4) ? 29 * fs : (29 * 4 + 28 * (fs - 4));
    const int ne    = (fs < 4) ? 29 : 28;
    const int fbase = ebase * EPOCH_F;

    // fill: pass p (0..1) -> class row p*32 + w*2 + ly, cols 4g..4g+3 (coalesced float4)
    int rl[2];
    const float* wp[2];
    #pragma unroll
    for (int p = 0; p < 2; p++) {
        rl[p] = p * 32 + w * 2 + ly;
        int row = cb * 64 + rl[p];
        if (row > NCLS - 1) row = NCLS - 1;
        wp[p] = W + (size_t)row * KROW + (size_t)fbase * 64 + g * 4;
    }
    const uint2* mp0 = g_meta + (size_t)(fbase + (tid >> 8)) * BATCH + (tid & 255);
    const uint2* mp1 = mp0 + 2 * BATCH;

    uint32_t acch[2][16];
    float    accf[2][16];
    #pragma unroll
    for (int k = 0; k < 2; k++)
        #pragma unroll
        for (int j = 0; j < 16; j++) { acch[k][j] = 0u; accf[k][j] = 0.f; }
    float rs[2] = {0.f, 0.f};

    // prologue prefetch: epoch 0 (f = fbase..fbase+3)
    float4 wv[2][EPOCH_F];
    #pragma unroll
    for (int p = 0; p < 2; p++)
        #pragma unroll
        for (int f4 = 0; f4 < EPOCH_F; f4++)
            wv[p][f4] = *(const float4*)(wp[p] + f4 * 64);
    uint2 mr0 = mp0[0], mr1 = mp1[0];

    for (int e = 0; e < ne; e++) {
        const int buf = e & 1;
        uint32_t* tbase = tiles + buf * (EPOCH_F * FTILE);

        // ---- fill all pair sub-tiles + rowsum (consumes wv) ----
        #pragma unroll
        for (int f4 = 0; f4 < EPOCH_F; f4++) {
            uint32_t* tb = tbase + f4 * FTILE;
            #pragma unroll
            for (int p = 0; p < 2; p++) {
                const float4 v = wv[p][f4];
                const float nx = __shfl_down_sync(0xffffffffu, v.x, 1);
                rs[p] += (v.x + v.y) + (v.z + v.w);
                uint32_t pr[4]; __half2 h;
                h = __floats2half2_rn(v.x, v.y);  pr[0] = *(uint32_t*)&h;
                h = __floats2half2_rn(v.y, v.z);  pr[1] = *(uint32_t*)&h;
                h = __floats2half2_rn(v.z, v.w);  pr[2] = *(uint32_t*)&h;
                h = __floats2half2_rn(v.w, nx);   pr[3] = *(uint32_t*)&h;
                if (g == 15) pr[3] = 0u;          // t=63 row: zero sink
                #pragma unroll
                for (int i = 0; i < 4; i++)
                    tb[(4 * g + i) * TSTRIDE + rl[p]] = pr[i];
            }
        }
        meta[buf * (EPOCH_F * 256) + tid]       = mr0;
        meta[buf * (EPOCH_F * 256) + tid + 512] = mr1;

        // ---- refill for epoch e+1 (LDG latency overlaps barrier + gather) ----
        if (e + 1 < ne) {
            const size_t off = (size_t)(EPOCH_F * (e + 1)) * 64;
            #pragma unroll
            for (int p = 0; p < 2; p++)
                #pragma unroll
                for (int f4 = 0; f4 < EPOCH_F; f4++)
                    wv[p][f4] = *(const float4*)(wp[p] + off + f4 * 64);
            mr0 = mp0[(size_t)(EPOCH_F * (e + 1)) * BATCH];
            mr1 = mp1[(size_t)(EPOCH_F * (e + 1)) * BATCH];
        }

        __syncthreads();

        // ---- gather 4 f's: per b: 2 conflict-free LDS.32 + 2 HFMA2 ----
        #pragma unroll
        for (int f4 = 0; f4 < EPOCH_F; f4++) {
            const char* tb = (const char*)(tbase + f4 * FTILE);
            const uint4* mb = (const uint4*)(meta + buf * (EPOCH_F * 256) + f4 * 256 + w * 16);
            #pragma unroll
            for (int q = 0; q < 8; q++) {
                const uint4 mq = mb[q];
                {
                    const int j = 2 * q;
                    const uint32_t* pb = (const uint32_t*)(tb + mq.x) + lane;
                    const uint32_t p0 = pb[0];
                    const uint32_t p1 = pb[32];
                    const __half2 l2 = *(const __half2*)&mq.y;
                    __half2 a0 = *(__half2*)&acch[0][j];
                    __half2 a1 = *(__half2*)&acch[1][j];
                    a0 = __hfma2(l2, *(const __half2*)&p0, a0);
                    a1 = __hfma2(l2, *(const __half2*)&p1, a1);
                    acch[0][j] = *(uint32_t*)&a0;
                    acch[1][j] = *(uint32_t*)&a1;
                }
                {
                    const int j = 2 * q + 1;
                    const uint32_t* pb = (const uint32_t*)(tb + mq.z) + lane;
                    const uint32_t p0 = pb[0];
                    const uint32_t p1 = pb[32];
                    const __half2 l2 = *(const __half2*)&mq.w;
                    __half2 a0 = *(__half2*)&acch[0][j];
                    __half2 a1 = *(__half2*)&acch[1][j];
                    a0 = __hfma2(l2, *(const __half2*)&p0, a0);
                    a1 = __hfma2(l2, *(const __half2*)&p1, a1);
                    acch[0][j] = *(uint32_t*)&a0;
                    acch[1][j] = *(uint32_t*)&a1;
                }
            }
        }

        // ---- drain f16 accumulators to fp32 every 4 epochs (16 f) ----
        if ((e & 3) == 3) {
            #pragma unroll
            for (int k = 0; k < 2; k++)
                #pragma unroll
                for (int j = 0; j < 16; j++) {
                    const float2 f2v = __half22float2(*(const __half2*)&acch[k][j]);
                    accf[k][j] += f2v.x + f2v.y;
                    acch[k][j] = 0u;
                }
        }
    }

    // ---- final drain (covers trailing epochs when ne % 4 != 0) ----
    #pragma unroll
    for (int k = 0; k < 2; k++)
        #pragma unroll
        for (int j = 0; j < 16; j++) {
            const float2 f2v = __half22float2(*(const __half2*)&acch[k][j]);
            accf[k][j] += f2v.x + f2v.y;
        }

    // ---- rowsum: reduce over the 16 column groups ----
    #pragma unroll
    for (int p = 0; p < 2; p++) {
        float r = rs[p];
        r += __shfl_xor_sync(0xffffffffu, r, 1);
        r += __shfl_xor_sync(0xffffffffu, r, 2);
        r += __shfl_xor_sync(0xffffffffu, r, 4);
        r += __shfl_xor_sync(0xffffffffu, r, 8);
        if (g == 0)
            g_rspart[fs * CPAD + cb * 64 + rl[p]] = r;
    }

    // ---- store partials (coalesced 128B per half) ----
    #pragma unroll
    for (int j = 0; j < 16; j++) {
        float* pp = g_part + ((size_t)fs * BATCH + w * 16 + j) * CPAD + cb * 64;
        pp[lane]      = accf[0][j];
        pp[lane + 32] = accf[1][j];
    }
}

// ---------------- Kernel 3: reduce partials + rowsum term ----------------
__global__ void __launch_bounds__(256) epi_k(const float* __restrict__ mn,
                                             const float* __restrict__ mx,
                                             float* __restrict__ out) {
    const int b = blockIdx.x;
    const float mnv = mn[0], mxv = mx[0];
    const float sc = mxv - mnv;
    for (int c = threadIdx.x; c < NCLS; c += 256) {
        float s = 0.f, rsum = 0.f;
        #pragma unroll
        for (int fsl = 0; fsl < FS; fsl++) {
            s    += g_part[((size_t)fsl * BATCH + b) * CPAD + c];
            rsum += g_rspart[fsl * CPAD + c];
        }
        out[(size_t)b * NCLS + c] = sc * s + mnv * rsum;
    }
}

// ---------------- launch ----------------
extern "C" void kernel_launch(void* const* d_in, const int* in_sizes, int n_in,
                              void* d_out, int out_size) {
    const float* x  = (const float*)d_in[0];
    const float* mn = (const float*)d_in[1];
    const float* mx = (const float*)d_in[2];
    const float* W  = (const float*)d_in[3];
    float* out = (float*)d_out;

    embed_k<<<dim3(32, 8), 1024>>>(x, mn, mx);

    cudaFuncSetAttribute(gather_k, cudaFuncAttributeMaxDynamicSharedMemorySize, SMEM_BYTES);
    gather_k<<<dim3(CB, FS), THREADS, SMEM_BYTES>>>(W);

    epi_k<<<BATCH, 256>>>(mn, mx, out);
}